// round 2
// baseline (speedup 1.0000x reference)
#include <cuda_runtime.h>
#include <cstdint>
#include <cstddef>

#define NMAX 50000
#define EMAX 800000
#define DF   128
#define NC   64

// ---------------- scratch (static device globals; no allocation) -------------
__device__ float g_dinv[NMAX];                 // rsqrt(degree)
__device__ float g_buf[(size_t)NMAX * DF];     // pre-scaled xw: dinv[row]*xw
__device__ int   g_cnt[NMAX];                  // in-degree (no self loop)
__device__ int   g_off[NMAX + 1];              // CSR offsets by dst
__device__ int   g_cur[NMAX];                  // fill cursors
__device__ int   g_csr[EMAX];                  // src ids grouped by dst
__device__ int   g_idx64;                      // 1 if edge_index is int64

// ---------------- edge dtype detection --------------------------------------
__global__ void k_detect(const void* edges) {
    if (threadIdx.x == 0 && blockIdx.x == 0) {
        const long long* p = (const long long*)edges;
        int ok = 1;
        #pragma unroll
        for (int i = 0; i < 16; i++) {
            long long v = p[i];
            if (v < 0 || v >= NMAX) ok = 0;
        }
        g_idx64 = ok;
    }
}

__device__ __forceinline__ int edge_at(const void* e, long long i, int is64) {
    return is64 ? (int)((const long long*)e)[i] : ((const int*)e)[i];
}

// ---------------- CSR construction -------------------------------------------
__global__ void k_zero(int n) {
    int i = blockIdx.x * blockDim.x + threadIdx.x;
    if (i < n) g_cnt[i] = 0;
}

__global__ void k_count(const void* __restrict__ edges, long long E) {
    long long i = (long long)blockIdx.x * blockDim.x + threadIdx.x;
    if (i < E) {
        int is64 = g_idx64;
        int d = edge_at(edges, E + i, is64);
        atomicAdd(&g_cnt[d], 1);
    }
}

// single-block exclusive scan + dinv computation
#define SCAN_T 1024
__global__ void __launch_bounds__(SCAN_T) k_scan(int n, int E) {
    __shared__ int sm[SCAN_T];
    int t = threadIdx.x;
    int chunk = (n + SCAN_T - 1) / SCAN_T;
    int lo = t * chunk, hi = lo + chunk; if (hi > n) hi = n;
    int s = 0;
    for (int i = lo; i < hi; i++) s += g_cnt[i];
    sm[t] = s;
    __syncthreads();
    #pragma unroll
    for (int o = 1; o < SCAN_T; o <<= 1) {
        int v = (t >= o) ? sm[t - o] : 0;
        __syncthreads();
        sm[t] += v;
        __syncthreads();
    }
    int base = sm[t] - s;   // exclusive prefix
    for (int i = lo; i < hi; i++) {
        g_off[i] = base;
        g_cur[i] = base;
        base += g_cnt[i];
        g_dinv[i] = rsqrtf((float)(g_cnt[i] + 1));  // +1 self loop
    }
    if (t == SCAN_T - 1) g_off[n] = E;
}

__global__ void k_fill(const void* __restrict__ edges, long long E) {
    long long i = (long long)blockIdx.x * blockDim.x + threadIdx.x;
    if (i < E) {
        int is64 = g_idx64;
        int s = edge_at(edges, i, is64);
        int d = edge_at(edges, E + i, is64);
        int pos = atomicAdd(&g_cur[d], 1);
        g_csr[pos] = s;
    }
}

// ---------------- GEMM + fused epilogue ---------------------------------------
// Y = X @ W ; writes g_buf[row] = dinv[row]*Y  and  e[row] = dinv^2*Y + b
// Tile: 64 rows x NOUT cols, 256 threads, each 2 rows x TN cols, f32x2 FMA.
#define SXLD 132

template<int NOUT, bool RELU>
__global__ void __launch_bounds__(256) k_gemm(const float* __restrict__ X,
                                              const float* __restrict__ W,
                                              const float* __restrict__ b,
                                              float* __restrict__ e, int n) {
    extern __shared__ float smf[];
    float* sW = smf;                  // 128 * NOUT
    float* sX = smf + 128 * NOUT;     // 64 * SXLD
    const int t = threadIdx.x;
    const int row0 = blockIdx.x * 64;

    for (int i = t * 4; i < 128 * NOUT; i += 1024)
        *(float4*)(sW + i) = *(const float4*)(W + i);

    for (int i = t * 4; i < 64 * 128; i += 1024) {
        int r = i >> 7, c = i & 127;
        int gr = row0 + r;
        float4 v = (gr < n) ? *(const float4*)(X + (size_t)gr * 128 + c)
                            : make_float4(0.f, 0.f, 0.f, 0.f);
        if (RELU) {
            v.x = fmaxf(v.x, 0.f); v.y = fmaxf(v.y, 0.f);
            v.z = fmaxf(v.z, 0.f); v.w = fmaxf(v.w, 0.f);
        }
        *(float4*)(sX + r * SXLD + c) = v;
    }
    __syncthreads();

    constexpr int TN  = NOUT / 8;   // 16 or 8
    constexpr int TNP = TN / 2;     // packed pairs
    const int rg = (t >> 3) * 2;
    const int cg = (t & 7) * TN;

    unsigned long long acc[2][TNP];
    #pragma unroll
    for (int i = 0; i < 2; i++)
        #pragma unroll
        for (int j = 0; j < TNP; j++) acc[i][j] = 0ull;

    #pragma unroll 4
    for (int k = 0; k < 128; k++) {
        unsigned long long wp[TNP];
        #pragma unroll
        for (int j = 0; j < TNP; j++)
            wp[j] = *(const unsigned long long*)(sW + k * NOUT + cg + 2 * j);
        #pragma unroll
        for (int i = 0; i < 2; i++) {
            float xv = sX[(rg + i) * SXLD + k];
            unsigned long long xp;
            asm("mov.b64 %0, {%1, %1};" : "=l"(xp) : "f"(xv));
            #pragma unroll
            for (int j = 0; j < TNP; j++)
                asm("fma.rn.f32x2 %0, %1, %2, %0;"
                    : "+l"(acc[i][j]) : "l"(xp), "l"(wp[j]));
        }
    }

    #pragma unroll
    for (int i = 0; i < 2; i++) {
        int r = row0 + rg + i;
        if (r < n) {
            float di = g_dinv[r];
            float di2 = di * di;
            #pragma unroll
            for (int j = 0; j < TNP; j++) {
                float lo, hi;
                asm("mov.b64 {%0, %1}, %2;" : "=f"(lo), "=f"(hi) : "l"(acc[i][j]));
                int c = cg + 2 * j;
                float2 bs; bs.x = di * lo; bs.y = di * hi;
                *(float2*)(g_buf + (size_t)r * NOUT + c) = bs;
                float2 ev;
                ev.x = fmaf(di2, lo, b[c]);
                ev.y = fmaf(di2, hi, b[c + 1]);
                *(float2*)(e + (size_t)r * NOUT + c) = ev;
            }
        }
    }
}

// ---------------- CSR gather: e[d] += dinv[d] * sum_s g_buf[s] -----------------
__global__ void k_gather128(float* __restrict__ e, int n) {
    int w = (blockIdx.x * blockDim.x + threadIdx.x) >> 5;
    int lane = threadIdx.x & 31;
    if (w >= n) return;
    int start = g_off[w], end = g_off[w + 1];
    float dd = g_dinv[w];
    float4 acc = make_float4(0.f, 0.f, 0.f, 0.f);
    for (int base = start; base < end; base += 32) {
        int m = end - base; if (m > 32) m = 32;
        int s = (lane < m) ? g_csr[base + lane] : 0;
        int j = 0;
        for (; j + 2 <= m; j += 2) {
            int s0 = __shfl_sync(0xffffffffu, s, j);
            int s1 = __shfl_sync(0xffffffffu, s, j + 1);
            float4 v0 = *(const float4*)(g_buf + (size_t)s0 * 128 + lane * 4);
            float4 v1 = *(const float4*)(g_buf + (size_t)s1 * 128 + lane * 4);
            acc.x += v0.x + v1.x; acc.y += v0.y + v1.y;
            acc.z += v0.z + v1.z; acc.w += v0.w + v1.w;
        }
        if (j < m) {
            int s0 = __shfl_sync(0xffffffffu, s, j);
            float4 v0 = *(const float4*)(g_buf + (size_t)s0 * 128 + lane * 4);
            acc.x += v0.x; acc.y += v0.y; acc.z += v0.z; acc.w += v0.w;
        }
    }
    float4 ev = *(float4*)(e + (size_t)w * 128 + lane * 4);
    ev.x = fmaf(dd, acc.x, ev.x); ev.y = fmaf(dd, acc.y, ev.y);
    ev.z = fmaf(dd, acc.z, ev.z); ev.w = fmaf(dd, acc.w, ev.w);
    *(float4*)(e + (size_t)w * 128 + lane * 4) = ev;
}

// ---------------- CSR gather (64-wide) fused with log_softmax ------------------
__global__ void k_gather64_lsm(float* __restrict__ e3, float* __restrict__ logp,
                               int n) {
    int w = (blockIdx.x * blockDim.x + threadIdx.x) >> 5;
    int lane = threadIdx.x & 31;
    if (w >= n) return;
    int start = g_off[w], end = g_off[w + 1];
    float dd = g_dinv[w];
    float2 acc = make_float2(0.f, 0.f);
    for (int base = start; base < end; base += 32) {
        int m = end - base; if (m > 32) m = 32;
        int s = (lane < m) ? g_csr[base + lane] : 0;
        int j = 0;
        for (; j + 2 <= m; j += 2) {
            int s0 = __shfl_sync(0xffffffffu, s, j);
            int s1 = __shfl_sync(0xffffffffu, s, j + 1);
            float2 v0 = *(const float2*)(g_buf + (size_t)s0 * 64 + lane * 2);
            float2 v1 = *(const float2*)(g_buf + (size_t)s1 * 64 + lane * 2);
            acc.x += v0.x + v1.x; acc.y += v0.y + v1.y;
        }
        if (j < m) {
            int s0 = __shfl_sync(0xffffffffu, s, j);
            float2 v0 = *(const float2*)(g_buf + (size_t)s0 * 64 + lane * 2);
            acc.x += v0.x; acc.y += v0.y;
        }
    }
    float2 ev = *(float2*)(e3 + (size_t)w * 64 + lane * 2);
    float r0 = fmaf(dd, acc.x, ev.x);
    float r1 = fmaf(dd, acc.y, ev.y);
    // write e3
    float2 out; out.x = r0; out.y = r1;
    *(float2*)(e3 + (size_t)w * 64 + lane * 2) = out;
    // fused log_softmax over 64 columns
    float mx = fmaxf(r0, r1);
    #pragma unroll
    for (int o = 16; o; o >>= 1) mx = fmaxf(mx, __shfl_xor_sync(0xffffffffu, mx, o));
    float sum = expf(r0 - mx) + expf(r1 - mx);
    #pragma unroll
    for (int o = 16; o; o >>= 1) sum += __shfl_xor_sync(0xffffffffu, sum, o);
    float lz = mx + logf(sum);
    float2 lp; lp.x = r0 - lz; lp.y = r1 - lz;
    *(float2*)(logp + (size_t)w * 64 + lane * 2) = lp;
}

// ---------------- launcher ------------------------------------------------------
extern "C" void kernel_launch(void* const* d_in, const int* in_sizes, int n_in,
                              void* d_out, int out_size) {
    const float* x  = (const float*)d_in[0];
    const void*  ed = d_in[1];
    const float* W1 = (const float*)d_in[2];
    const float* b1 = (const float*)d_in[3];
    const float* W2 = (const float*)d_in[4];
    const float* b2 = (const float*)d_in[5];
    const float* W3 = (const float*)d_in[6];
    const float* b3 = (const float*)d_in[7];

    int       N = in_sizes[0] / DF;
    long long E = (long long)in_sizes[1] / 2;

    float* out  = (float*)d_out;
    float* logp = out;
    float* e1   = out + (size_t)N * NC;
    float* e2   = e1 + (size_t)N * DF;
    float* e3   = e2 + (size_t)N * DF;

    const int smem128 = (128 * 128 + 64 * SXLD) * 4;   // ~99.3 KB
    const int smem64  = (128 * 64  + 64 * SXLD) * 4;   // ~66.5 KB
    cudaFuncSetAttribute((const void*)k_gemm<128, false>,
                         cudaFuncAttributeMaxDynamicSharedMemorySize, smem128);
    cudaFuncSetAttribute((const void*)k_gemm<128, true>,
                         cudaFuncAttributeMaxDynamicSharedMemorySize, smem128);
    cudaFuncSetAttribute((const void*)k_gemm<64, true>,
                         cudaFuncAttributeMaxDynamicSharedMemorySize, smem64);

    int nb_nodes = (N + 255) / 256;
    int nb_edges = (int)((E + 255) / 256);
    int nb_gemm  = (N + 63) / 64;
    int nb_gat   = (N + 7) / 8;       // 8 warps (nodes) per 256-thread block

    // ---- CSR build + normalization ----
    k_detect<<<1, 32>>>(ed);
    k_zero<<<nb_nodes, 256>>>(N);
    k_count<<<nb_edges, 256>>>(ed, E);
    k_scan<<<1, SCAN_T>>>(N, (int)E);
    k_fill<<<nb_edges, 256>>>(ed, E);

    // ---- layer 1 ----
    k_gemm<128, false><<<nb_gemm, 256, smem128>>>(x, W1, b1, e1, N);
    k_gather128<<<nb_gat, 256>>>(e1, N);

    // ---- layer 2 (relu fused into X load) ----
    k_gemm<128, true><<<nb_gemm, 256, smem128>>>(e1, W2, b2, e2, N);
    k_gather128<<<nb_gat, 256>>>(e2, N);

    // ---- layer 3 + fused log_softmax ----
    k_gemm<64, true><<<nb_gemm, 256, smem64>>>(e2, W3, b3, e3, N);
    k_gather64_lsm<<<nb_gat, 256>>>(e3, logp, N);
}

// round 3
// speedup vs baseline: 3.1452x; 3.1452x over previous
#include <cuda_runtime.h>
#include <cstdint>
#include <cstddef>

#define NMAX 50000
#define EMAX 800000
#define DF   128
#define NC   64

// ---------------- scratch (static device globals; no allocation) -------------
__device__ float g_dinv[NMAX];                 // rsqrt(degree)
__device__ float g_buf[(size_t)NMAX * DF];     // pre-scaled xw: dinv[row]*xw
__device__ int   g_cnt[NMAX];                  // in-degree (no self loop)
__device__ int   g_scan[NMAX];                 // inclusive per-block scan
__device__ int   g_bsum[128];                  // block sums / exclusive prefixes
__device__ int   g_off[NMAX + 1];              // CSR offsets by dst
__device__ int   g_cur[NMAX];                  // fill cursors
__device__ int   g_csr[EMAX];                  // src ids grouped by dst
__device__ int   g_idx64;                      // 1 if edge_index is int64

// ---------------- edge dtype detection --------------------------------------
__global__ void k_detect(const void* edges) {
    if (threadIdx.x == 0 && blockIdx.x == 0) {
        const long long* p = (const long long*)edges;
        int ok = 1;
        #pragma unroll
        for (int i = 0; i < 16; i++) {
            long long v = p[i];
            if (v < 0 || v >= NMAX) ok = 0;
        }
        g_idx64 = ok;
    }
}

__device__ __forceinline__ int edge_at(const void* e, long long i, int is64) {
    return is64 ? (int)((const long long*)e)[i] : ((const int*)e)[i];
}

// ---------------- CSR construction -------------------------------------------
__global__ void k_zero(int n) {
    int i = blockIdx.x * blockDim.x + threadIdx.x;
    if (i < n) g_cnt[i] = 0;
}

__global__ void k_count(const void* __restrict__ edges, long long E) {
    long long i = (long long)blockIdx.x * blockDim.x + threadIdx.x;
    if (i < E) {
        int is64 = g_idx64;
        int d = edge_at(edges, E + i, is64);
        atomicAdd(&g_cnt[d], 1);
    }
}

// pass 1: per-block inclusive scan of g_cnt (1024 elems per block)
__global__ void __launch_bounds__(1024) k_scan1(int n) {
    __shared__ int sm[1024];
    int t = threadIdx.x;
    int i = blockIdx.x * 1024 + t;
    int v = (i < n) ? g_cnt[i] : 0;
    sm[t] = v;
    __syncthreads();
    #pragma unroll
    for (int o = 1; o < 1024; o <<= 1) {
        int u = (t >= o) ? sm[t - o] : 0;
        __syncthreads();
        sm[t] += u;
        __syncthreads();
    }
    if (i < n) g_scan[i] = sm[t];
    if (t == 1023) g_bsum[blockIdx.x] = sm[1023];
}

// pass 2: exclusive scan of block sums (nb <= 128), single tiny block
__global__ void k_scan2(int nb) {
    __shared__ int sm[128];
    int t = threadIdx.x;
    int v = (t < nb) ? g_bsum[t] : 0;
    sm[t] = v;
    __syncthreads();
    #pragma unroll
    for (int o = 1; o < 128; o <<= 1) {
        int u = (t >= o) ? sm[t - o] : 0;
        __syncthreads();
        sm[t] += u;
        __syncthreads();
    }
    if (t < nb) g_bsum[t] = sm[t] - v;   // exclusive
}

// pass 3: apply prefixes; produce g_off, g_cur, g_dinv
__global__ void __launch_bounds__(1024) k_scan3(int n, int E) {
    int i = blockIdx.x * 1024 + threadIdx.x;
    if (i < n) {
        int incl = g_scan[i] + g_bsum[blockIdx.x];
        int c = g_cnt[i];
        int off = incl - c;
        g_off[i] = off;
        g_cur[i] = off;
        g_dinv[i] = rsqrtf((float)(c + 1));   // +1 self loop
        if (i == n - 1) g_off[n] = E;
    }
}

__global__ void k_fill(const void* __restrict__ edges, long long E) {
    long long i = (long long)blockIdx.x * blockDim.x + threadIdx.x;
    if (i < E) {
        int is64 = g_idx64;
        int s = edge_at(edges, i, is64);
        int d = edge_at(edges, E + i, is64);
        int pos = atomicAdd(&g_cur[d], 1);
        g_csr[pos] = s;
    }
}

// ---------------- GEMM: g_buf[row] = dinv[row] * (X @ W)[row] ------------------
// Tile: 64 rows x NOUT cols, 256 threads. Each thread: 4 rows x (NOUT/16) col
// pairs at stride 32, packed fma.rn.f32x2. Conflict-free W LDS.64.
#define SXLD 132

template<int NOUT, bool RELU>
__global__ void __launch_bounds__(256) k_gemm(const float* __restrict__ X,
                                              const float* __restrict__ W,
                                              int n) {
    extern __shared__ float smf[];
    float* sW = smf;                  // 128 * NOUT
    float* sX = smf + 128 * NOUT;     // 64 * SXLD
    const int t = threadIdx.x;
    const int row0 = blockIdx.x * 64;

    for (int i = t * 4; i < 128 * NOUT; i += 1024)
        *(float4*)(sW + i) = *(const float4*)(W + i);

    for (int i = t * 4; i < 64 * 128; i += 1024) {
        int r = i >> 7, c = i & 127;
        int gr = row0 + r;
        float4 v = (gr < n) ? *(const float4*)(X + (size_t)gr * 128 + c)
                            : make_float4(0.f, 0.f, 0.f, 0.f);
        if (RELU) {
            v.x = fmaxf(v.x, 0.f); v.y = fmaxf(v.y, 0.f);
            v.z = fmaxf(v.z, 0.f); v.w = fmaxf(v.w, 0.f);
        }
        *(float4*)(sX + r * SXLD + c) = v;
    }
    __syncthreads();

    constexpr int TP = NOUT / 32;        // col pairs per thread: 4 (128) / 2 (64)
    const int rg = (t >> 4) * 4;         // 16 row groups * 4 rows = 64
    const int c0 = (t & 15) * 2;         // pair base; +32*p strided groups

    unsigned long long acc[4][TP];
    #pragma unroll
    for (int i = 0; i < 4; i++)
        #pragma unroll
        for (int p = 0; p < TP; p++) acc[i][p] = 0ull;

    #pragma unroll 4
    for (int k = 0; k < 128; k++) {
        unsigned long long wp[TP];
        #pragma unroll
        for (int p = 0; p < TP; p++)
            wp[p] = *(const unsigned long long*)(sW + k * NOUT + c0 + 32 * p);
        #pragma unroll
        for (int i = 0; i < 4; i++) {
            float xv = sX[(rg + i) * SXLD + k];
            unsigned long long xp;
            asm("mov.b64 %0, {%1, %1};" : "=l"(xp) : "f"(xv));
            #pragma unroll
            for (int p = 0; p < TP; p++)
                asm("fma.rn.f32x2 %0, %1, %2, %0;"
                    : "+l"(acc[i][p]) : "l"(xp), "l"(wp[p]));
        }
    }

    #pragma unroll
    for (int i = 0; i < 4; i++) {
        int r = row0 + rg + i;
        if (r < n) {
            float di = g_dinv[r];
            #pragma unroll
            for (int p = 0; p < TP; p++) {
                float lo, hi;
                asm("mov.b64 {%0, %1}, %2;" : "=f"(lo), "=f"(hi) : "l"(acc[i][p]));
                float2 bs; bs.x = di * lo; bs.y = di * hi;
                *(float2*)(g_buf + (size_t)r * NOUT + c0 + 32 * p) = bs;
            }
        }
    }
}

// ---------------- CSR gather: e[d] = dd*(self + sum_s buf[s]) + b --------------
__global__ void k_gather128(const float* __restrict__ bias,
                            float* __restrict__ e, int n) {
    int w = (blockIdx.x * blockDim.x + threadIdx.x) >> 5;
    int lane = threadIdx.x & 31;
    if (w >= n) return;
    int j = g_off[w], end = g_off[w + 1];
    float dd = g_dinv[w];
    float4 a0 = *(const float4*)(g_buf + (size_t)w * 128 + lane * 4); // self
    float4 a1 = make_float4(0.f, 0.f, 0.f, 0.f);
    float4 a2 = make_float4(0.f, 0.f, 0.f, 0.f);
    float4 a3 = make_float4(0.f, 0.f, 0.f, 0.f);
    for (; j + 4 <= end; j += 4) {
        int s0 = __ldg(&g_csr[j]);
        int s1 = __ldg(&g_csr[j + 1]);
        int s2 = __ldg(&g_csr[j + 2]);
        int s3 = __ldg(&g_csr[j + 3]);
        float4 v0 = *(const float4*)(g_buf + (size_t)s0 * 128 + lane * 4);
        float4 v1 = *(const float4*)(g_buf + (size_t)s1 * 128 + lane * 4);
        float4 v2 = *(const float4*)(g_buf + (size_t)s2 * 128 + lane * 4);
        float4 v3 = *(const float4*)(g_buf + (size_t)s3 * 128 + lane * 4);
        a0.x += v0.x; a0.y += v0.y; a0.z += v0.z; a0.w += v0.w;
        a1.x += v1.x; a1.y += v1.y; a1.z += v1.z; a1.w += v1.w;
        a2.x += v2.x; a2.y += v2.y; a2.z += v2.z; a2.w += v2.w;
        a3.x += v3.x; a3.y += v3.y; a3.z += v3.z; a3.w += v3.w;
    }
    for (; j < end; j++) {
        int s0 = __ldg(&g_csr[j]);
        float4 v0 = *(const float4*)(g_buf + (size_t)s0 * 128 + lane * 4);
        a0.x += v0.x; a0.y += v0.y; a0.z += v0.z; a0.w += v0.w;
    }
    a0.x += a1.x + a2.x + a3.x;
    a0.y += a1.y + a2.y + a3.y;
    a0.z += a1.z + a2.z + a3.z;
    a0.w += a1.w + a2.w + a3.w;
    float4 bb = *(const float4*)(bias + lane * 4);
    float4 o;
    o.x = fmaf(dd, a0.x, bb.x); o.y = fmaf(dd, a0.y, bb.y);
    o.z = fmaf(dd, a0.z, bb.z); o.w = fmaf(dd, a0.w, bb.w);
    *(float4*)(e + (size_t)w * 128 + lane * 4) = o;
}

// ---------------- CSR gather (64-wide) + fused log_softmax ---------------------
__global__ void k_gather64_lsm(const float* __restrict__ bias,
                               float* __restrict__ e3,
                               float* __restrict__ logp, int n) {
    int w = (blockIdx.x * blockDim.x + threadIdx.x) >> 5;
    int lane = threadIdx.x & 31;
    if (w >= n) return;
    int j = g_off[w], end = g_off[w + 1];
    float dd = g_dinv[w];
    float2 a0 = *(const float2*)(g_buf + (size_t)w * 64 + lane * 2);  // self
    float2 a1 = make_float2(0.f, 0.f);
    float2 a2 = make_float2(0.f, 0.f);
    float2 a3 = make_float2(0.f, 0.f);
    for (; j + 4 <= end; j += 4) {
        int s0 = __ldg(&g_csr[j]);
        int s1 = __ldg(&g_csr[j + 1]);
        int s2 = __ldg(&g_csr[j + 2]);
        int s3 = __ldg(&g_csr[j + 3]);
        float2 v0 = *(const float2*)(g_buf + (size_t)s0 * 64 + lane * 2);
        float2 v1 = *(const float2*)(g_buf + (size_t)s1 * 64 + lane * 2);
        float2 v2 = *(const float2*)(g_buf + (size_t)s2 * 64 + lane * 2);
        float2 v3 = *(const float2*)(g_buf + (size_t)s3 * 64 + lane * 2);
        a0.x += v0.x; a0.y += v0.y;
        a1.x += v1.x; a1.y += v1.y;
        a2.x += v2.x; a2.y += v2.y;
        a3.x += v3.x; a3.y += v3.y;
    }
    for (; j < end; j++) {
        int s0 = __ldg(&g_csr[j]);
        float2 v0 = *(const float2*)(g_buf + (size_t)s0 * 64 + lane * 2);
        a0.x += v0.x; a0.y += v0.y;
    }
    a0.x += a1.x + a2.x + a3.x;
    a0.y += a1.y + a2.y + a3.y;
    float2 bb = *(const float2*)(bias + lane * 2);
    float r0 = fmaf(dd, a0.x, bb.x);
    float r1 = fmaf(dd, a0.y, bb.y);
    float2 ev; ev.x = r0; ev.y = r1;
    *(float2*)(e3 + (size_t)w * 64 + lane * 2) = ev;
    // fused log_softmax over 64 columns
    float mx = fmaxf(r0, r1);
    #pragma unroll
    for (int o = 16; o; o >>= 1) mx = fmaxf(mx, __shfl_xor_sync(0xffffffffu, mx, o));
    float sum = expf(r0 - mx) + expf(r1 - mx);
    #pragma unroll
    for (int o = 16; o; o >>= 1) sum += __shfl_xor_sync(0xffffffffu, sum, o);
    float lz = mx + logf(sum);
    float2 lp; lp.x = r0 - lz; lp.y = r1 - lz;
    *(float2*)(logp + (size_t)w * 64 + lane * 2) = lp;
}

// ---------------- launcher ------------------------------------------------------
extern "C" void kernel_launch(void* const* d_in, const int* in_sizes, int n_in,
                              void* d_out, int out_size) {
    const float* x  = (const float*)d_in[0];
    const void*  ed = d_in[1];
    const float* W1 = (const float*)d_in[2];
    const float* b1 = (const float*)d_in[3];
    const float* W2 = (const float*)d_in[4];
    const float* b2 = (const float*)d_in[5];
    const float* W3 = (const float*)d_in[6];
    const float* b3 = (const float*)d_in[7];

    int       N = in_sizes[0] / DF;
    long long E = (long long)in_sizes[1] / 2;

    float* out  = (float*)d_out;
    float* logp = out;
    float* e1   = out + (size_t)N * NC;
    float* e2   = e1 + (size_t)N * DF;
    float* e3   = e2 + (size_t)N * DF;

    const int smem128 = (128 * 128 + 64 * SXLD) * 4;   // ~99.3 KB
    const int smem64  = (128 * 64  + 64 * SXLD) * 4;   // ~66.5 KB
    cudaFuncSetAttribute((const void*)k_gemm<128, false>,
                         cudaFuncAttributeMaxDynamicSharedMemorySize, smem128);
    cudaFuncSetAttribute((const void*)k_gemm<128, true>,
                         cudaFuncAttributeMaxDynamicSharedMemorySize, smem128);
    cudaFuncSetAttribute((const void*)k_gemm<64, true>,
                         cudaFuncAttributeMaxDynamicSharedMemorySize, smem64);

    int nb_nodes = (N + 255) / 256;
    int nb_edges = (int)((E + 255) / 256);
    int nb_scan  = (N + 1023) / 1024;
    int nb_gemm  = (N + 63) / 64;
    int nb_gat   = (N + 7) / 8;       // 8 warps (nodes) per 256-thread block

    // ---- CSR build + normalization ----
    k_detect<<<1, 32>>>(ed);
    k_zero<<<nb_nodes, 256>>>(N);
    k_count<<<nb_edges, 256>>>(ed, E);
    k_scan1<<<nb_scan, 1024>>>(N);
    k_scan2<<<1, 128>>>(nb_scan);
    k_scan3<<<nb_scan, 1024>>>(N, (int)E);
    k_fill<<<nb_edges, 256>>>(ed, E);

    // ---- layer 1 ----
    k_gemm<128, false><<<nb_gemm, 256, smem128>>>(x, W1, N);
    k_gather128<<<nb_gat, 256>>>(b1, e1, N);

    // ---- layer 2 (relu fused into X load) ----
    k_gemm<128, true><<<nb_gemm, 256, smem128>>>(e1, W2, N);
    k_gather128<<<nb_gat, 256>>>(b2, e2, N);

    // ---- layer 3 + fused log_softmax ----
    k_gemm<64, true><<<nb_gemm, 256, smem64>>>(e2, W3, N);
    k_gather64_lsm<<<nb_gat, 256>>>(b3, e3, logp, N);
}

// round 5
// speedup vs baseline: 4.1442x; 1.3176x over previous
#include <cuda_runtime.h>
#include <cuda_bf16.h>
#include <cstdint>
#include <cstddef>

#define NMAX 50000
#define EMAX 800000
#define DF   128
#define NC   64

// ---------------- scratch (static device globals; no allocation) -------------
__device__ float g_dinv[NMAX];
__device__ float g_buf[(size_t)NMAX * DF];
__device__ int   g_cnt[NMAX];
__device__ int   g_scan[NMAX];
__device__ int   g_bsum[128];
__device__ int   g_off[NMAX + 1];
__device__ int   g_cur[NMAX];
__device__ int   g_csr[EMAX];
__device__ int   g_idx64;
// W^T split to bf16 hi/lo, padded layout [n*136 + k] halves: [layer][hi/lo]
__device__ __align__(16) unsigned char g_wt[3][2][128 * 272];

// ---------------- edge utils ---------------------------------------------------
__device__ __forceinline__ int edge_at(const void* e, long long i, int is64) {
    return is64 ? (int)((const long long*)e)[i] : ((const int*)e)[i];
}

__global__ void k_init(const void* edges, int n) {
    int i = blockIdx.x * blockDim.x + threadIdx.x;
    if (i < n) g_cnt[i] = 0;
    if (i == 0) {
        const long long* p = (const long long*)edges;
        int ok = 1;
        #pragma unroll
        for (int j = 0; j < 16; j++) {
            long long v = p[j];
            if (v < 0 || v >= NMAX) ok = 0;
        }
        g_idx64 = ok;
    }
}

__global__ void k_count(const void* __restrict__ edges, long long E) {
    long long i = (long long)blockIdx.x * blockDim.x + threadIdx.x;
    if (i < E) atomicAdd(&g_cnt[edge_at(edges, E + i, g_idx64)], 1);
}

__global__ void __launch_bounds__(1024) k_scan1(int n) {
    __shared__ int sm[1024];
    int t = threadIdx.x;
    int i = blockIdx.x * 1024 + t;
    int v = (i < n) ? g_cnt[i] : 0;
    sm[t] = v;
    __syncthreads();
    #pragma unroll
    for (int o = 1; o < 1024; o <<= 1) {
        int u = (t >= o) ? sm[t - o] : 0;
        __syncthreads();
        sm[t] += u;
        __syncthreads();
    }
    if (i < n) g_scan[i] = sm[t];
    if (t == 1023) g_bsum[blockIdx.x] = sm[1023];
}

__global__ void k_scan2(int nb) {
    __shared__ int sm[128];
    int t = threadIdx.x;
    int v = (t < nb) ? g_bsum[t] : 0;
    sm[t] = v;
    __syncthreads();
    #pragma unroll
    for (int o = 1; o < 128; o <<= 1) {
        int u = (t >= o) ? sm[t - o] : 0;
        __syncthreads();
        sm[t] += u;
        __syncthreads();
    }
    if (t < nb) g_bsum[t] = sm[t] - v;
}

__global__ void __launch_bounds__(1024) k_scan3(int n, int E) {
    int i = blockIdx.x * 1024 + threadIdx.x;
    if (i < n) {
        int incl = g_scan[i] + g_bsum[blockIdx.x];
        int c = g_cnt[i];
        int off = incl - c;
        g_off[i] = off;
        g_cur[i] = off;
        g_dinv[i] = rsqrtf((float)(c + 1));
        if (i == n - 1) g_off[n] = E;
    }
}

__global__ void k_fill(const void* __restrict__ edges, long long E) {
    long long i = (long long)blockIdx.x * blockDim.x + threadIdx.x;
    if (i < E) {
        int is64 = g_idx64;
        int s = edge_at(edges, i, is64);
        int d = edge_at(edges, E + i, is64);
        g_csr[atomicAdd(&g_cur[d], 1)] = s;
    }
}

// ------------- W prep: W^T, split fp32 -> bf16 hi/lo, padded [n][k] -----------
__global__ void k_prepw(const float* __restrict__ W1, const float* __restrict__ W2,
                        const float* __restrict__ W3) {
    int idx = blockIdx.x * blockDim.x + threadIdx.x;
    if (idx >= 16384 * 2 + 8192) return;
    int layer, nout, e;
    const float* W;
    if (idx < 16384)       { layer = 0; nout = 128; e = idx;         W = W1; }
    else if (idx < 32768)  { layer = 1; nout = 128; e = idx - 16384; W = W2; }
    else                   { layer = 2; nout = 64;  e = idx - 32768; W = W3; }
    int k = e / nout, nn = e % nout;
    float w = W[k * nout + nn];
    __nv_bfloat16 hi = __float2bfloat16(w);
    __nv_bfloat16 lo = __float2bfloat16(w - __bfloat162float(hi));
    uint32_t off = (uint32_t)(nn * 136 + k) * 2;
    *(__nv_bfloat16*)&g_wt[layer][0][off] = hi;
    *(__nv_bfloat16*)&g_wt[layer][1][off] = lo;
}

// ------------- HMMA GEMM: g_buf[r] = dinv[r] * (X @ W)[r] ----------------------
// mma.sync m16n8k16 bf16, 3-term split. Block = 128 rows x NOUT, 8 warps.
__device__ __forceinline__ void lm_x4(uint32_t& r0, uint32_t& r1, uint32_t& r2,
                                      uint32_t& r3, uint32_t a) {
    asm volatile("ldmatrix.sync.aligned.m8n8.x4.shared.b16 {%0,%1,%2,%3}, [%4];"
                 : "=r"(r0), "=r"(r1), "=r"(r2), "=r"(r3) : "r"(a));
}
__device__ __forceinline__ void lm_x2(uint32_t& r0, uint32_t& r1, uint32_t a) {
    asm volatile("ldmatrix.sync.aligned.m8n8.x2.shared.b16 {%0,%1}, [%2];"
                 : "=r"(r0), "=r"(r1) : "r"(a));
}
__device__ __forceinline__ void mma_bf16(float* c, uint32_t a0, uint32_t a1,
                                         uint32_t a2, uint32_t a3,
                                         uint32_t b0, uint32_t b1) {
    asm volatile("mma.sync.aligned.m16n8k16.row.col.f32.bf16.bf16.f32 "
                 "{%0,%1,%2,%3}, {%4,%5,%6,%7}, {%8,%9}, {%0,%1,%2,%3};"
                 : "+f"(c[0]), "+f"(c[1]), "+f"(c[2]), "+f"(c[3])
                 : "r"(a0), "r"(a1), "r"(a2), "r"(a3), "r"(b0), "r"(b1));
}

template<int NOUT, bool RELU>
__global__ void __launch_bounds__(256) k_hgemm(const float* __restrict__ X,
                                               int layer, int n) {
    extern __shared__ char sm[];
    constexpr int BSZ = NOUT * 272;          // bf16 [n][k] stride 272B
    constexpr int B_HI = 0;
    constexpr int B_LO = BSZ;
    constexpr int A_HI = 2 * BSZ;
    constexpr int A_LO = 2 * BSZ + 128 * 272;
    const int t = threadIdx.x;
    const int row0 = blockIdx.x * 128;

    uint32_t sb;
    asm("{ .reg .u64 u; cvta.to.shared.u64 u, %1; cvt.u32.u64 %0, u; }"
        : "=r"(sb) : "l"(sm));

    // copy W tiles (already padded/transposed/split)
    {
        const float4* s0 = (const float4*)&g_wt[layer][0][0];
        const float4* s1 = (const float4*)&g_wt[layer][1][0];
        float4* d0 = (float4*)(sm + B_HI);
        float4* d1 = (float4*)(sm + B_LO);
        #pragma unroll
        for (int i = t; i < BSZ / 16; i += 256) { d0[i] = s0[i]; d1[i] = s1[i]; }
    }

    // A: load X rows, optional relu, split hi/lo, store padded [row][k]
    {
        const int row = t >> 1;
        const int c0 = (t & 1) * 64;
        const int gr = row0 + row;
        const float4* xr = (const float4*)(X + (size_t)gr * 128 + c0);
        char* ah = sm + A_HI + row * 272 + c0 * 2;
        char* al = sm + A_LO + row * 272 + c0 * 2;
        #pragma unroll 4
        for (int q = 0; q < 16; q++) {
            float4 v = (gr < n) ? xr[q] : make_float4(0.f, 0.f, 0.f, 0.f);
            if (RELU) {
                v.x = fmaxf(v.x, 0.f); v.y = fmaxf(v.y, 0.f);
                v.z = fmaxf(v.z, 0.f); v.w = fmaxf(v.w, 0.f);
            }
            __nv_bfloat162 h0, h1, l0, l1;
            h0.x = __float2bfloat16(v.x); h0.y = __float2bfloat16(v.y);
            h1.x = __float2bfloat16(v.z); h1.y = __float2bfloat16(v.w);
            l0.x = __float2bfloat16(v.x - __bfloat162float(h0.x));
            l0.y = __float2bfloat16(v.y - __bfloat162float(h0.y));
            l1.x = __float2bfloat16(v.z - __bfloat162float(h1.x));
            l1.y = __float2bfloat16(v.w - __bfloat162float(h1.y));
            *(__nv_bfloat162*)(ah + q * 8)     = h0;
            *(__nv_bfloat162*)(ah + q * 8 + 4) = h1;
            *(__nv_bfloat162*)(al + q * 8)     = l0;
            *(__nv_bfloat162*)(al + q * 8 + 4) = l1;
        }
    }
    __syncthreads();

    const int warp = t >> 5, lane = t & 31;
    constexpr int NCH = NOUT / 8;
    float acc[NCH][4];
    #pragma unroll
    for (int nc = 0; nc < NCH; nc++)
        #pragma unroll
        for (int q = 0; q < 4; q++) acc[nc][q] = 0.f;

    // ldmatrix lane address components
    const uint32_t aRow = sb + A_HI
        + (uint32_t)(warp * 16 + (lane & 7) + ((lane >> 3) & 1) * 8) * 272
        + (lane >> 4) * 16;
    const int bl = lane & 15;
    const uint32_t bRow = sb + B_HI + (uint32_t)(bl & 7) * 272 + ((bl >> 3) & 1) * 16;

    #pragma unroll
    for (int kc = 0; kc < 8; kc++) {
        uint32_t ah0, ah1, ah2, ah3, al0, al1, al2, al3;
        lm_x4(ah0, ah1, ah2, ah3, aRow + kc * 32);
        lm_x4(al0, al1, al2, al3, aRow + kc * 32 + (A_LO - A_HI));
        #pragma unroll
        for (int nc = 0; nc < NCH; nc++) {
            uint32_t bh0, bh1, bl0, bl1;
            uint32_t ba = bRow + (uint32_t)nc * 8 * 272 + kc * 32;
            lm_x2(bh0, bh1, ba);
            lm_x2(bl0, bl1, ba + BSZ);
            mma_bf16(acc[nc], ah0, ah1, ah2, ah3, bh0, bh1);
            mma_bf16(acc[nc], ah0, ah1, ah2, ah3, bl0, bl1);
            mma_bf16(acc[nc], al0, al1, al2, al3, bh0, bh1);
        }
    }

    // epilogue: scale by dinv, store fp32
    {
        const int r0 = row0 + warp * 16 + (lane >> 2);
        const int r1 = r0 + 8;
        const int cb = (lane & 3) * 2;
        const float dv0 = (r0 < n) ? g_dinv[r0] : 0.f;
        const float dv1 = (r1 < n) ? g_dinv[r1] : 0.f;
        #pragma unroll
        for (int nc = 0; nc < NCH; nc++) {
            int col = nc * 8 + cb;
            if (r0 < n) {
                float2 o; o.x = dv0 * acc[nc][0]; o.y = dv0 * acc[nc][1];
                *(float2*)(g_buf + (size_t)r0 * NOUT + col) = o;
            }
            if (r1 < n) {
                float2 o; o.x = dv1 * acc[nc][2]; o.y = dv1 * acc[nc][3];
                *(float2*)(g_buf + (size_t)r1 * NOUT + col) = o;
            }
        }
    }
}

// ---------------- CSR gather: e[d] = dd*(self + sum_s buf[s]) + b --------------
__global__ void k_gather128(const float* __restrict__ bias,
                            float* __restrict__ e, int n) {
    int w = (blockIdx.x * blockDim.x + threadIdx.x) >> 5;
    int lane = threadIdx.x & 31;
    if (w >= n) return;
    int j = g_off[w], end = g_off[w + 1];
    float dd = g_dinv[w];
    float4 a0 = *(const float4*)(g_buf + (size_t)w * 128 + lane * 4);
    float4 a1 = make_float4(0.f, 0.f, 0.f, 0.f);
    float4 a2 = make_float4(0.f, 0.f, 0.f, 0.f);
    float4 a3 = make_float4(0.f, 0.f, 0.f, 0.f);
    for (; j + 4 <= end; j += 4) {
        int s0 = __ldg(&g_csr[j]);
        int s1 = __ldg(&g_csr[j + 1]);
        int s2 = __ldg(&g_csr[j + 2]);
        int s3 = __ldg(&g_csr[j + 3]);
        float4 v0 = *(const float4*)(g_buf + (size_t)s0 * 128 + lane * 4);
        float4 v1 = *(const float4*)(g_buf + (size_t)s1 * 128 + lane * 4);
        float4 v2 = *(const float4*)(g_buf + (size_t)s2 * 128 + lane * 4);
        float4 v3 = *(const float4*)(g_buf + (size_t)s3 * 128 + lane * 4);
        a0.x += v0.x; a0.y += v0.y; a0.z += v0.z; a0.w += v0.w;
        a1.x += v1.x; a1.y += v1.y; a1.z += v1.z; a1.w += v1.w;
        a2.x += v2.x; a2.y += v2.y; a2.z += v2.z; a2.w += v2.w;
        a3.x += v3.x; a3.y += v3.y; a3.z += v3.z; a3.w += v3.w;
    }
    for (; j < end; j++) {
        int s0 = __ldg(&g_csr[j]);
        float4 v0 = *(const float4*)(g_buf + (size_t)s0 * 128 + lane * 4);
        a0.x += v0.x; a0.y += v0.y; a0.z += v0.z; a0.w += v0.w;
    }
    a0.x += a1.x + a2.x + a3.x;
    a0.y += a1.y + a2.y + a3.y;
    a0.z += a1.z + a2.z + a3.z;
    a0.w += a1.w + a2.w + a3.w;
    float4 bb = *(const float4*)(bias + lane * 4);
    float4 o;
    o.x = fmaf(dd, a0.x, bb.x); o.y = fmaf(dd, a0.y, bb.y);
    o.z = fmaf(dd, a0.z, bb.z); o.w = fmaf(dd, a0.w, bb.w);
    *(float4*)(e + (size_t)w * 128 + lane * 4) = o;
}

__global__ void k_gather64_lsm(const float* __restrict__ bias,
                               float* __restrict__ e3,
                               float* __restrict__ logp, int n) {
    int w = (blockIdx.x * blockDim.x + threadIdx.x) >> 5;
    int lane = threadIdx.x & 31;
    if (w >= n) return;
    int j = g_off[w], end = g_off[w + 1];
    float dd = g_dinv[w];
    float2 a0 = *(const float2*)(g_buf + (size_t)w * 64 + lane * 2);
    float2 a1 = make_float2(0.f, 0.f);
    float2 a2 = make_float2(0.f, 0.f);
    float2 a3 = make_float2(0.f, 0.f);
    for (; j + 4 <= end; j += 4) {
        int s0 = __ldg(&g_csr[j]);
        int s1 = __ldg(&g_csr[j + 1]);
        int s2 = __ldg(&g_csr[j + 2]);
        int s3 = __ldg(&g_csr[j + 3]);
        float2 v0 = *(const float2*)(g_buf + (size_t)s0 * 64 + lane * 2);
        float2 v1 = *(const float2*)(g_buf + (size_t)s1 * 64 + lane * 2);
        float2 v2 = *(const float2*)(g_buf + (size_t)s2 * 64 + lane * 2);
        float2 v3 = *(const float2*)(g_buf + (size_t)s3 * 64 + lane * 2);
        a0.x += v0.x; a0.y += v0.y;
        a1.x += v1.x; a1.y += v1.y;
        a2.x += v2.x; a2.y += v2.y;
        a3.x += v3.x; a3.y += v3.y;
    }
    for (; j < end; j++) {
        int s0 = __ldg(&g_csr[j]);
        float2 v0 = *(const float2*)(g_buf + (size_t)s0 * 64 + lane * 2);
        a0.x += v0.x; a0.y += v0.y;
    }
    a0.x += a1.x + a2.x + a3.x;
    a0.y += a1.y + a2.y + a3.y;
    float2 bb = *(const float2*)(bias + lane * 2);
    float r0 = fmaf(dd, a0.x, bb.x);
    float r1 = fmaf(dd, a0.y, bb.y);
    float2 ev; ev.x = r0; ev.y = r1;
    *(float2*)(e3 + (size_t)w * 64 + lane * 2) = ev;
    float mx = fmaxf(r0, r1);
    #pragma unroll
    for (int o = 16; o; o >>= 1) mx = fmaxf(mx, __shfl_xor_sync(0xffffffffu, mx, o));
    float sum = expf(r0 - mx) + expf(r1 - mx);
    #pragma unroll
    for (int o = 16; o; o >>= 1) sum += __shfl_xor_sync(0xffffffffu, sum, o);
    float lz = mx + logf(sum);
    float2 lp; lp.x = r0 - lz; lp.y = r1 - lz;
    *(float2*)(logp + (size_t)w * 64 + lane * 2) = lp;
}

// ---------------- launcher ------------------------------------------------------
extern "C" void kernel_launch(void* const* d_in, const int* in_sizes, int n_in,
                              void* d_out, int out_size) {
    const float* x  = (const float*)d_in[0];
    const void*  ed = d_in[1];
    const float* W1 = (const float*)d_in[2];
    const float* b1 = (const float*)d_in[3];
    const float* W2 = (const float*)d_in[4];
    const float* b2 = (const float*)d_in[5];
    const float* W3 = (const float*)d_in[6];
    const float* b3 = (const float*)d_in[7];

    int       N = in_sizes[0] / DF;
    long long E = (long long)in_sizes[1] / 2;

    float* out  = (float*)d_out;
    float* logp = out;
    float* e1   = out + (size_t)N * NC;
    float* e2   = e1 + (size_t)N * DF;
    float* e3   = e2 + (size_t)N * DF;

    const int smem128 = 2 * 128 * 272 + 2 * 128 * 272;  // 139264
    const int smem64  = 2 * 64 * 272 + 2 * 128 * 272;   // 104448
    cudaFuncSetAttribute((const void*)k_hgemm<128, false>,
                         cudaFuncAttributeMaxDynamicSharedMemorySize, smem128);
    cudaFuncSetAttribute((const void*)k_hgemm<128, true>,
                         cudaFuncAttributeMaxDynamicSharedMemorySize, smem128);
    cudaFuncSetAttribute((const void*)k_hgemm<64, true>,
                         cudaFuncAttributeMaxDynamicSharedMemorySize, smem64);

    int nb_nodes = (N + 255) / 256;
    int nb_edges = (int)((E + 255) / 256);
    int nb_scan  = (N + 1023) / 1024;
    int nb_gemm  = (N + 127) / 128;
    int nb_gat   = (N + 7) / 8;

    // ---- CSR build + W prep ----
    k_init<<<nb_nodes, 256>>>(ed, N);
    k_prepw<<<(16384 * 2 + 8192 + 255) / 256, 256>>>(W1, W2, W3);
    k_count<<<nb_edges, 256>>>(ed, E);
    k_scan1<<<nb_scan, 1024>>>(N);
    k_scan2<<<1, 128>>>(nb_scan);
    k_scan3<<<nb_scan, 1024>>>(N, (int)E);
    k_fill<<<nb_edges, 256>>>(ed, E);

    // ---- layer 1 ----
    k_hgemm<128, false><<<nb_gemm, 256, smem128>>>(x, 0, N);
    k_gather128<<<nb_gat, 256>>>(b1, e1, N);

    // ---- layer 2 (relu fused into A conversion) ----
    k_hgemm<128, true><<<nb_gemm, 256, smem128>>>(e1, 1, N);
    k_gather128<<<nb_gat, 256>>>(b2, e2, N);

    // ---- layer 3 + fused log_softmax ----
    k_hgemm<64, true><<<nb_gemm, 256, smem64>>>(e2, 2, N);
    k_gather64_lsm<<<nb_gat, 256>>>(b3, e3, logp, N);
}